// round 14
// baseline (speedup 1.0000x reference)
#include <cuda_runtime.h>
#include <cuda_fp16.h>

#define N_NODES   100000
#define N_EDGES   1600000
#define N_TOT     1700000
#define N_GRAPHSX 2048
#define H         100
#define H4        25
#define K0        33
#define K0P       36
#define BN_EPS    1e-5f
#define NBLK_SCAN 98
#define WSL       (104 * 112)   // weight staging slice (layers 1-3; layer0 uses 104*48)

// ---------------- scratch ----------------
__device__ __align__(16) __half g_hx[N_NODES * K0P];    // aggregated x (fp16)
__device__ __align__(16) __half g_Y[N_NODES * H];       // Y ping
__device__ __align__(16) __half g_Y2[N_NODES * H];      // Y pong
__device__ __align__(16) __half g_Wh[4 * WSL];          // transposed fp16 weights
__device__ __align__(16) float  g_bnS[4 * H];
__device__ __align__(16) float  g_bnT[4 * H];
__device__ float g_gsum[N_GRAPHSX];
__device__ float g_dis[N_NODES];
__device__ int   g_colptr[N_NODES + 1];
__device__ int   g_cursor[N_NODES];
__device__ int   g_csrsrc[N_TOT];
__device__ int   g_batch[N_NODES];
__device__ int   g_bsum[128];
__device__ int   g_boff[128];
__device__ int   g_is64;

// ---------------- init + probe ----------------
__global__ void k_init(const unsigned* __restrict__ ebuf) {
    int i = blockIdx.x * blockDim.x + threadIdx.x;
    if (i < N_NODES) g_cursor[i] = 1;
    if (i < N_GRAPHSX) g_gsum[i] = 0.f;
    if (i == 0) {
        int all0 = 1;
        for (int j = 1; j < 128; j += 2) all0 &= (ebuf[j] == 0u);
        g_is64 = all0;
    }
}

// degree count + batch conversion (merged)
__global__ void k_count(const void* __restrict__ ebuf, const void* __restrict__ bbuf) {
    int i = blockIdx.x * blockDim.x + threadIdx.x;
    int is64 = g_is64;
    if (i < N_EDGES) {
        int d = is64 ? (int)((const long long*)ebuf)[N_EDGES + i]
                     : ((const int*)ebuf)[N_EDGES + i];
        atomicAdd(&g_cursor[d], 1);
    }
    if (i < N_NODES)
        g_batch[i] = is64 ? (int)((const long long*)bbuf)[i] : ((const int*)bbuf)[i];
}

// ---------------- scans (R9 verbatim) ----------------
__global__ void k_scan_a() {
    __shared__ int red[256];
    int b = blockIdx.x, t = threadIdx.x;
    int base = b * 1024 + t * 4;
    int s = 0;
#pragma unroll
    for (int j = 0; j < 4; j++) {
        int idx = base + j;
        if (idx < N_NODES) {
            int c = g_cursor[idx];
            s += c;
            g_dis[idx] = rsqrtf((float)c);
        }
    }
    red[t] = s; __syncthreads();
    for (int off = 128; off > 0; off >>= 1) {
        if (t < off) red[t] += red[t + off];
        __syncthreads();
    }
    if (t == 0) g_bsum[b] = red[0];
}

__global__ void k_scan_b() {
    int lane = threadIdx.x;
    int base = lane * 4;
    int c[4]; int s = 0;
#pragma unroll
    for (int j = 0; j < 4; j++) {
        c[j] = (base + j < NBLK_SCAN) ? g_bsum[base + j] : 0;
        s += c[j];
    }
    int x = s;
#pragma unroll
    for (int off = 1; off < 32; off <<= 1) {
        int y = __shfl_up_sync(0xffffffffu, x, off);
        if (lane >= off) x += y;
    }
    int acc = x - s;
#pragma unroll
    for (int j = 0; j < 4; j++) {
        if (base + j < NBLK_SCAN) g_boff[base + j] = acc;
        acc += c[j];
    }
    if (lane == 31) g_colptr[N_NODES] = x;
}

__global__ void k_scan_c() {
    __shared__ int wsum[8], woff[8];
    int b = blockIdx.x, t = threadIdx.x;
    int base = b * 1024 + t * 4;
    int v[4];
#pragma unroll
    for (int j = 0; j < 4; j++) {
        int idx = base + j;
        v[j] = (idx < N_NODES) ? g_cursor[idx] : 0;
    }
    int s = v[0] + v[1] + v[2] + v[3];
    int lane = t & 31, w = t >> 5;
    int x = s;
#pragma unroll
    for (int off = 1; off < 32; off <<= 1) {
        int y = __shfl_up_sync(0xffffffffu, x, off);
        if (lane >= off) x += y;
    }
    if (lane == 31) wsum[w] = x;
    __syncthreads();
    if (t == 0) { int a = 0; for (int i = 0; i < 8; i++) { woff[i] = a; a += wsum[i]; } }
    __syncthreads();
    int excl = (x - s) + woff[w] + g_boff[b];
#pragma unroll
    for (int j = 0; j < 4; j++) {
        int idx = base + j;
        if (idx < N_NODES) {
            g_colptr[idx] = excl;
            g_csrsrc[excl] = idx;      // self loop
            g_cursor[idx] = excl + 1;
        }
        excl += v[j];
    }
}

__global__ void k_filledges(const void* __restrict__ ebuf) {
    int e = blockIdx.x * blockDim.x + threadIdx.x;
    if (e >= N_EDGES) return;
    int s, d;
    if (g_is64) {
        const long long* p = (const long long*)ebuf;
        s = (int)p[e]; d = (int)p[N_EDGES + e];
    } else {
        const int* p = (const int*)ebuf;
        s = p[e]; d = p[N_EDGES + e];
    }
    int pos = atomicAdd(&g_cursor[d], 1);
    g_csrsrc[pos] = s;
}

// ---------------- fused prep: BN consts + all weight transposes -----------
__global__ void k_prep(const float* __restrict__ W0, const float* __restrict__ Ws,
                       const float* __restrict__ bias, const float* __restrict__ gamma,
                       const float* __restrict__ beta, const float* __restrict__ mean,
                       const float* __restrict__ var) {
    int i = blockIdx.x * blockDim.x + threadIdx.x;
    if (i < 4 * H) {
        float s = gamma[i] * rsqrtf(var[i] + BN_EPS);
        g_bnS[i] = s;
        g_bnT[i] = (bias[i] - mean[i]) * s + beta[i];
        return;
    }
    int i0 = i - 4 * H;
    if (i0 < 104 * 48) {                     // layer 0: [104][48] <- W0[33][100]
        int n = i0 / 48, k = i0 % 48;
        g_Wh[i0] = (n < H && k < K0) ? __float2half(W0[k * H + n]) : __float2half(0.f);
        return;
    }
    int i1 = i0 - 104 * 48;
    if (i1 < 3 * WSL) {                      // layers 1-3: [104][112] <- Ws[l][100][100]
        int l = i1 / WSL, r = i1 % WSL;
        int n = r / 112, k = r % 112;
        g_Wh[WSL * (l + 1) + r] = (n < H && k < H)
            ? __float2half(Ws[l * H * H + k * H + n]) : __float2half(0.f);
    }
}

// ---------------- layer-0 aggregate (fused prescale): x -> g_hx fp16 -------
__global__ void k_agg0(const float* __restrict__ x) {
    int gwarp = (blockIdx.x * blockDim.x + threadIdx.x) >> 5;
    int lane = threadIdx.x & 31;
    if (gwarp >= N_NODES) return;
    int n = gwarp;
    int beg = g_colptr[n], end = g_colptr[n + 1];
    float a = 0.f, a32 = 0.f;
    for (int i = beg; i < end; i++) {
        int s = g_csrsrc[i];                 // broadcast
        float ds = g_dis[s];                 // broadcast
        a = fmaf(ds, x[s * K0 + lane], a);
        if (lane == 0) a32 = fmaf(ds, x[s * K0 + 32], a32);
    }
    float dn = g_dis[n];
    g_hx[n * K0P + lane] = __float2half(a * dn);
    if (lane == 0) g_hx[n * K0P + 32] = __float2half(a32 * dn);
    else if (lane < 4) g_hx[n * K0P + 32 + lane] = __float2half(0.f);
}

// ============ shared MMA core helper (proven R9 fragment layout) ===========
// computes acc[13][4] += A(16 rows r0.., smem KS stride) * B(104 rows)
#define MMA_CORE(As, Bs, KS, NKSTEP)                                          \
    _Pragma("unroll")                                                         \
    for (int ks = 0; ks < (NKSTEP); ks++) {                                   \
        int kb = ks * 16 + t * 2;                                             \
        unsigned a0 = *(unsigned*)&(As)[(r0 + g) * (KS) + kb];                \
        unsigned a1 = *(unsigned*)&(As)[(r0 + g + 8) * (KS) + kb];            \
        unsigned a2 = *(unsigned*)&(As)[(r0 + g) * (KS) + kb + 8];            \
        unsigned a3 = *(unsigned*)&(As)[(r0 + g + 8) * (KS) + kb + 8];        \
        _Pragma("unroll")                                                     \
        for (int j = 0; j < 13; j++) {                                        \
            int nr = j * 8 + g;                                               \
            unsigned b0 = *(unsigned*)&(Bs)[nr * (KS) + kb];                  \
            unsigned b1 = *(unsigned*)&(Bs)[nr * (KS) + kb + 8];              \
            asm volatile(                                                     \
                "mma.sync.aligned.m16n8k16.row.col.f32.f16.f16.f32 "          \
                "{%0,%1,%2,%3}, {%4,%5,%6,%7}, {%8,%9}, {%0,%1,%2,%3};"       \
                : "+f"(acc[j][0]), "+f"(acc[j][1]), "+f"(acc[j][2]), "+f"(acc[j][3]) \
                : "r"(a0), "r"(a1), "r"(a2), "r"(a3), "r"(b0), "r"(b1));      \
        }                                                                     \
    }

// ---------------- G01: GEMM0(BN0+ReLU, smem-resident h0) + GEMM1 -> g_Y ----
__global__ void __launch_bounds__(256) k_G01(const __half* __restrict__ W0p,
                                             const __half* __restrict__ W1p) {
    extern __shared__ __half smem[];
    __half* As2 = smem;                 // [128][120] h0 tile (persistent)
    __half* rg  = smem + 128 * 120;     // union region: phase A = As0|Bs0, phase B = Bs1
    __half* As0 = rg;                   // [128][56]
    __half* Bs0 = rg + 128 * 56;        // [104][56]
    __half* Bs1 = rg;                   // [104][120]
    int row0 = blockIdx.x * 128;
    int tid = threadIdx.x;
    int warp = tid >> 5, lane = tid & 31;
    int g = lane >> 2, t = lane & 3;
    int r0 = warp * 16;
    const __half2 z2 = __float2half2_rn(0.f);

    // phase A fills
    for (int i = tid; i < 128 * 28; i += 256) {         // As0: 28 half2/row (56 halves)
        int r = i / 28, c2 = i % 28;
        int gr = row0 + r;
        __half2 v = (c2 < 18 && gr < N_NODES) ? ((const __half2*)g_hx)[gr * 18 + c2] : z2;
        *(__half2*)&As0[r * 56 + c2 * 2] = v;
    }
    for (int i = tid; i < 104 * 24; i += 256) {         // Bs0 from [104][48] staging
        int nn = i / 24, c2 = i % 24;
        *(__half2*)&Bs0[nn * 56 + c2 * 2] = ((const __half2*)W0p)[i];
    }
    __syncthreads();

    float acc[13][4];
#pragma unroll
    for (int j = 0; j < 13; j++)
#pragma unroll
        for (int c = 0; c < 4; c++) acc[j][c] = 0.f;
    MMA_CORE(As0, Bs0, 56, 3)

    // epilogue 0: BN0+ReLU -> As2 (smem h0), rows local (unguarded)
#pragma unroll
    for (int j = 0; j < 13; j++) {
        int c = j * 8 + t * 2;
        if (c >= H) continue;
        float Sx = g_bnS[c], Sy = g_bnS[c + 1];
        float Tx = g_bnT[c], Ty = g_bnT[c + 1];
        {
            float ox = fmaxf(fmaf(acc[j][0], Sx, Tx), 0.f);
            float oy = fmaxf(fmaf(acc[j][1], Sy, Ty), 0.f);
            *(__half2*)&As2[(r0 + g) * 120 + c] = __floats2half2_rn(ox, oy);
        }
        {
            float ox = fmaxf(fmaf(acc[j][2], Sx, Tx), 0.f);
            float oy = fmaxf(fmaf(acc[j][3], Sy, Ty), 0.f);
            *(__half2*)&As2[(r0 + g + 8) * 120 + c] = __floats2half2_rn(ox, oy);
        }
    }
    // zero pad cols 100..111 of As2
    for (int i = tid; i < 128 * 6; i += 256) {
        int r = i / 6, c2 = i % 6;
        *(__half2*)&As2[r * 120 + 100 + c2 * 2] = z2;
    }
    __syncthreads();
    // phase B fill: Bs1 over the union region
    for (int i = tid; i < 104 * 60; i += 256) {
        int nn = i / 60, c2 = i % 60;
        __half2 v = (c2 < 56) ? ((const __half2*)W1p)[nn * 56 + c2] : z2;
        *(__half2*)&Bs1[nn * 120 + c2 * 2] = v;
    }
    __syncthreads();

#pragma unroll
    for (int j = 0; j < 13; j++)
#pragma unroll
        for (int c = 0; c < 4; c++) acc[j][c] = 0.f;
    MMA_CORE(As2, Bs1, 120, 7)

    int gr0 = row0 + r0 + g, gr1 = gr0 + 8;
    float d0 = (gr0 < N_NODES) ? g_dis[gr0] : 0.f;
    float d1 = (gr1 < N_NODES) ? g_dis[gr1] : 0.f;
#pragma unroll
    for (int j = 0; j < 13; j++) {
        int c = j * 8 + t * 2;
        if (c >= H) continue;
        if (gr0 < N_NODES)
            *(__half2*)&g_Y[gr0 * H + c] = __floats2half2_rn(acc[j][0] * d0, acc[j][1] * d0);
        if (gr1 < N_NODES)
            *(__half2*)&g_Y[gr1 * H + c] = __floats2half2_rn(acc[j][2] * d1, acc[j][3] * d1);
    }
}

// ---------------- fused agg(BN_l+ReLU) + GEMM_{l+1}: Yin -> Yout -----------
template <int LBN>
__global__ void __launch_bounds__(256) k_fused(const __half* __restrict__ Wp,
                                               const __half* __restrict__ Yin,
                                               __half* __restrict__ Yout) {
    extern __shared__ __half smem[];
    __half* As = smem;                  // [128][120] h tile
    __half* Bs = smem + 128 * 120;      // [104][120]
    int row0 = blockIdx.x * 128;
    int tid = threadIdx.x;
    int warp = tid >> 5, lane = tid & 31;
    const __half2 z2 = __float2half2_rn(0.f);

    // ---- agg phase: warp handles 16 local rows ----
    const uint2* Y2 = (const uint2*)Yin;
#pragma unroll 1
    for (int k = 0; k < 16; k++) {
        int lr = warp * 16 + k;
        int n = row0 + lr;
        float ox = 0.f, oy = 0.f, oz = 0.f, ow = 0.f;
        if (n < N_NODES && lane < H4) {
            int beg = g_colptr[n], end = g_colptr[n + 1];
            float a0x=0.f,a0y=0.f,a0z=0.f,a0w=0.f;
            float a1x=0.f,a1y=0.f,a1z=0.f,a1w=0.f;
            float a2x=0.f,a2y=0.f,a2z=0.f,a2w=0.f;
            float a3x=0.f,a3y=0.f,a3z=0.f,a3w=0.f;
            int i = beg;
            for (; i + 3 < end; i += 4) {
                int s0 = g_csrsrc[i], s1 = g_csrsrc[i+1], s2 = g_csrsrc[i+2], s3 = g_csrsrc[i+3];
                uint2 u0 = Y2[s0 * H4 + lane];
                uint2 u1 = Y2[s1 * H4 + lane];
                uint2 u2 = Y2[s2 * H4 + lane];
                uint2 u3 = Y2[s3 * H4 + lane];
                float2 p;
                p = __half22float2(*(__half2*)&u0.x); a0x += p.x; a0y += p.y;
                p = __half22float2(*(__half2*)&u0.y); a0z += p.x; a0w += p.y;
                p = __half22float2(*(__half2*)&u1.x); a1x += p.x; a1y += p.y;
                p = __half22float2(*(__half2*)&u1.y); a1z += p.x; a1w += p.y;
                p = __half22float2(*(__half2*)&u2.x); a2x += p.x; a2y += p.y;
                p = __half22float2(*(__half2*)&u2.y); a2z += p.x; a2w += p.y;
                p = __half22float2(*(__half2*)&u3.x); a3x += p.x; a3y += p.y;
                p = __half22float2(*(__half2*)&u3.y); a3z += p.x; a3w += p.y;
            }
            for (; i < end; i++) {
                int s0 = g_csrsrc[i];
                uint2 u0 = Y2[s0 * H4 + lane];
                float2 p;
                p = __half22float2(*(__half2*)&u0.x); a0x += p.x; a0y += p.y;
                p = __half22float2(*(__half2*)&u0.y); a0z += p.x; a0w += p.y;
            }
            float ax = (a0x + a1x) + (a2x + a3x);
            float ay = (a0y + a1y) + (a2y + a3y);
            float az = (a0z + a1z) + (a2z + a3z);
            float aw = (a0w + a1w) + (a2w + a3w);
            float d = g_dis[n];
            int c = LBN * H + lane * 4;
            float4 S = *(const float4*)&g_bnS[c];
            float4 T = *(const float4*)&g_bnT[c];
            ox = fmaxf(fmaf(ax * d, S.x, T.x), 0.f);
            oy = fmaxf(fmaf(ay * d, S.y, T.y), 0.f);
            oz = fmaxf(fmaf(az * d, S.z, T.z), 0.f);
            ow = fmaxf(fmaf(aw * d, S.w, T.w), 0.f);
        }
        if (lane < 30) {
            __half2 h0 = __floats2half2_rn(ox, oy);   // zeros for lanes>=25 / invalid rows
            __half2 h1 = __floats2half2_rn(oz, ow);
            uint2 u; u.x = *(unsigned*)&h0; u.y = *(unsigned*)&h1;
            *(uint2*)&As[lr * 120 + lane * 4] = u;
        }
    }
    __syncthreads();
    for (int i = tid; i < 104 * 60; i += 256) {
        int nn = i / 60, c2 = i % 60;
        __half2 v = (c2 < 56) ? ((const __half2*)Wp)[nn * 56 + c2] : z2;
        *(__half2*)&Bs[nn * 120 + c2 * 2] = v;
    }
    __syncthreads();

    int g = lane >> 2, t = lane & 3;
    int r0 = warp * 16;
    float acc[13][4];
#pragma unroll
    for (int j = 0; j < 13; j++)
#pragma unroll
        for (int c = 0; c < 4; c++) acc[j][c] = 0.f;
    MMA_CORE(As, Bs, 120, 7)

    int gr0 = row0 + r0 + g, gr1 = gr0 + 8;
    float d0 = (gr0 < N_NODES) ? g_dis[gr0] : 0.f;
    float d1 = (gr1 < N_NODES) ? g_dis[gr1] : 0.f;
#pragma unroll
    for (int j = 0; j < 13; j++) {
        int c = j * 8 + t * 2;
        if (c >= H) continue;
        if (gr0 < N_NODES)
            *(__half2*)&Yout[gr0 * H + c] = __floats2half2_rn(acc[j][0] * d0, acc[j][1] * d0);
        if (gr1 < N_NODES)
            *(__half2*)&Yout[gr1 * H + c] = __floats2half2_rn(acc[j][2] * d1, acc[j][3] * d1);
    }
}

// ---------------- final aggregation + pool (R9 verbatim, LAST=1 path) ------
__global__ void k_aggpool(const float* __restrict__ hW) {
    int gwarp = (blockIdx.x * blockDim.x + threadIdx.x) >> 5;
    int lane = threadIdx.x & 31;
    if (gwarp >= N_NODES) return;
    int n = gwarp;
    float ox = 0.f, oy = 0.f, oz = 0.f, ow = 0.f;
    if (lane < H4) {
        int beg = g_colptr[n], end = g_colptr[n + 1];
        const uint2* Y2 = (const uint2*)g_Y;
        float a0x=0.f,a0y=0.f,a0z=0.f,a0w=0.f;
        float a1x=0.f,a1y=0.f,a1z=0.f,a1w=0.f;
        float a2x=0.f,a2y=0.f,a2z=0.f,a2w=0.f;
        float a3x=0.f,a3y=0.f,a3z=0.f,a3w=0.f;
        int i = beg;
        for (; i + 3 < end; i += 4) {
            int s0 = g_csrsrc[i], s1 = g_csrsrc[i+1], s2 = g_csrsrc[i+2], s3 = g_csrsrc[i+3];
            uint2 u0 = Y2[s0 * H4 + lane];
            uint2 u1 = Y2[s1 * H4 + lane];
            uint2 u2 = Y2[s2 * H4 + lane];
            uint2 u3 = Y2[s3 * H4 + lane];
            float2 p;
            p = __half22float2(*(__half2*)&u0.x); a0x += p.x; a0y += p.y;
            p = __half22float2(*(__half2*)&u0.y); a0z += p.x; a0w += p.y;
            p = __half22float2(*(__half2*)&u1.x); a1x += p.x; a1y += p.y;
            p = __half22float2(*(__half2*)&u1.y); a1z += p.x; a1w += p.y;
            p = __half22float2(*(__half2*)&u2.x); a2x += p.x; a2y += p.y;
            p = __half22float2(*(__half2*)&u2.y); a2z += p.x; a2w += p.y;
            p = __half22float2(*(__half2*)&u3.x); a3x += p.x; a3y += p.y;
            p = __half22float2(*(__half2*)&u3.y); a3z += p.x; a3w += p.y;
        }
        for (; i < end; i++) {
            int s0 = g_csrsrc[i];
            uint2 u0 = Y2[s0 * H4 + lane];
            float2 p;
            p = __half22float2(*(__half2*)&u0.x); a0x += p.x; a0y += p.y;
            p = __half22float2(*(__half2*)&u0.y); a0z += p.x; a0w += p.y;
        }
        float ax = (a0x + a1x) + (a2x + a3x);
        float ay = (a0y + a1y) + (a2y + a3y);
        float az = (a0z + a1z) + (a2z + a3z);
        float aw = (a0w + a1w) + (a2w + a3w);
        float d = g_dis[n];
        int c = 3 * H + lane * 4;
        float4 S = *(const float4*)&g_bnS[c];
        float4 T = *(const float4*)&g_bnT[c];
        ox = fmaf(ax * d, S.x, T.x);
        oy = fmaf(ay * d, S.y, T.y);
        oz = fmaf(az * d, S.z, T.z);
        ow = fmaf(aw * d, S.w, T.w);
    }
    float s = 0.f;
    if (lane < H4) {
        float4 w4 = ((const float4*)hW)[lane];
        s = ox * w4.x + oy * w4.y + oz * w4.z + ow * w4.w;
    }
#pragma unroll
    for (int off = 16; off > 0; off >>= 1)
        s += __shfl_down_sync(0xffffffffu, s, off);
    if (lane == 0) atomicAdd(&g_gsum[g_batch[n]], s);
}

// ---------------- finish: bias + LeakyReLU ----------------
__global__ void k_finish(const float* __restrict__ hb, float* __restrict__ out) {
    int g = blockIdx.x * blockDim.x + threadIdx.x;
    if (g >= N_GRAPHSX) return;
    float o = g_gsum[g] + hb[0];
    out[g] = (o >= 0.f) ? o : 0.1f * o;
}

// ---------------- launch ----------------
extern "C" void kernel_launch(void* const* d_in, const int* in_sizes, int n_in,
                              void* d_out, int out_size) {
    const float* x      = (const float*)d_in[0];
    const void*  ei     = d_in[1];
    const void*  batch  = d_in[2];
    const float* W0     = (const float*)d_in[3];
    const float* Ws     = (const float*)d_in[4];
    const float* biases = (const float*)d_in[5];
    const float* gamma  = (const float*)d_in[6];
    const float* beta   = (const float*)d_in[7];
    const float* mean   = (const float*)d_in[8];
    const float* var    = (const float*)d_in[9];
    const float* headW  = (const float*)d_in[10];
    const float* headb  = (const float*)d_in[11];
    float* out = (float*)d_out;

    const int smem_g01   = (128 * 120 + 128 * 56 + 104 * 56) * 2;  // 56704
    const int smem_fused = (128 + 104) * 120 * 2;                   // 55680
    cudaFuncSetAttribute(k_G01,       cudaFuncAttributeMaxDynamicSharedMemorySize, smem_g01);
    cudaFuncSetAttribute(k_fused<1>,  cudaFuncAttributeMaxDynamicSharedMemorySize, smem_fused);
    cudaFuncSetAttribute(k_fused<2>,  cudaFuncAttributeMaxDynamicSharedMemorySize, smem_fused);

    __half *whp = nullptr, *yp = nullptr, *y2p = nullptr;
    cudaGetSymbolAddress((void**)&whp, g_Wh);
    cudaGetSymbolAddress((void**)&yp,  g_Y);
    cudaGetSymbolAddress((void**)&y2p, g_Y2);

    k_init<<<(N_NODES + 255) / 256, 256>>>((const unsigned*)ei);
    k_count<<<(N_EDGES + 255) / 256, 256>>>(ei, batch);
    k_scan_a<<<NBLK_SCAN, 256>>>();
    k_scan_b<<<1, 32>>>();
    k_scan_c<<<NBLK_SCAN, 256>>>();
    k_filledges<<<(N_EDGES + 255) / 256, 256>>>(ei);
    k_prep<<<(4 * H + 104 * 48 + 3 * WSL + 255) / 256, 256>>>(W0, Ws, biases, gamma, beta, mean, var);

    int tile_blocks = (N_NODES + 127) / 128;
    int agg_blocks  = (N_NODES * 32 + 255) / 256;

    k_agg0<<<agg_blocks, 256>>>(x);
    k_G01<<<tile_blocks, 256, smem_g01>>>(whp, whp + WSL);          // -> g_Y (Y1)
    k_fused<1><<<tile_blocks, 256, smem_fused>>>(whp + 2 * WSL, yp, y2p);  // -> g_Y2 (Y2)
    k_fused<2><<<tile_blocks, 256, smem_fused>>>(whp + 3 * WSL, y2p, yp);  // -> g_Y (Y3)
    k_aggpool<<<agg_blocks, 256>>>(headW);
    k_finish<<<(N_GRAPHSX + 255) / 256, 256>>>(headb, out);
}

// round 15
// speedup vs baseline: 1.1188x; 1.1188x over previous
#include <cuda_runtime.h>
#include <cuda_fp16.h>

#define N_NODES   100000
#define N_EDGES   1600000
#define N_TOT     1700000
#define N_GRAPHSX 2048
#define H         100
#define H4        25
#define K0        33
#define K0P       36
#define BN_EPS    1e-5f
#define NBLK_SCAN 98
#define WSL       (104 * 112)   // weight staging slice

// ---------------- scratch ----------------
__device__ __align__(16) __half g_hx[N_NODES * K0P];    // aggregated x (fp16)
__device__ __align__(16) __half g_h[N_NODES * H];       // h (fp16)
__device__ __align__(16) __half g_Y[N_NODES * H];       // Y = dis*(h@W) (fp16)
__device__ __align__(16) __half g_Wh[4 * WSL];          // transposed fp16 weights
__device__ __align__(16) float  g_bnS[4 * H];
__device__ __align__(16) float  g_bnT[4 * H];
__device__ float g_gsum[N_GRAPHSX];
__device__ float g_dis[N_NODES];
__device__ int   g_colptr[N_NODES + 1];
__device__ int   g_cursor[N_NODES];
__device__ int   g_csrsrc[N_TOT];
__device__ int   g_batch[N_NODES];
__device__ int   g_bsum[128];
__device__ int   g_boff[128];
__device__ int   g_is64;

// ---------------- init + probe ----------------
__global__ void k_init(const unsigned* __restrict__ ebuf) {
    int i = blockIdx.x * blockDim.x + threadIdx.x;
    if (i < N_NODES) g_cursor[i] = 1;
    if (i < N_GRAPHSX) g_gsum[i] = 0.f;
    if (i == 0) {
        int all0 = 1;
        for (int j = 1; j < 128; j += 2) all0 &= (ebuf[j] == 0u);
        g_is64 = all0;
    }
}

__global__ void k_count(const void* __restrict__ ebuf) {
    int e = blockIdx.x * blockDim.x + threadIdx.x;
    if (e >= N_EDGES) return;
    int d = g_is64 ? (int)((const long long*)ebuf)[N_EDGES + e]
                   : ((const int*)ebuf)[N_EDGES + e];
    atomicAdd(&g_cursor[d], 1);
}

__global__ void k_gptr(const void* __restrict__ bbuf) {
    int i = blockIdx.x * blockDim.x + threadIdx.x;
    if (i >= N_NODES) return;
    int b = g_is64 ? (int)((const long long*)bbuf)[i] : ((const int*)bbuf)[i];
    g_batch[i] = b;
}

// ---------------- scans ----------------
__global__ void k_scan_a() {
    __shared__ int red[256];
    int b = blockIdx.x, t = threadIdx.x;
    int base = b * 1024 + t * 4;
    int s = 0;
#pragma unroll
    for (int j = 0; j < 4; j++) {
        int idx = base + j;
        if (idx < N_NODES) {
            int c = g_cursor[idx];
            s += c;
            g_dis[idx] = rsqrtf((float)c);
        }
    }
    red[t] = s; __syncthreads();
    for (int off = 128; off > 0; off >>= 1) {
        if (t < off) red[t] += red[t + off];
        __syncthreads();
    }
    if (t == 0) g_bsum[b] = red[0];
}

__global__ void k_scan_b() {
    int lane = threadIdx.x;
    int base = lane * 4;
    int c[4]; int s = 0;
#pragma unroll
    for (int j = 0; j < 4; j++) {
        c[j] = (base + j < NBLK_SCAN) ? g_bsum[base + j] : 0;
        s += c[j];
    }
    int x = s;
#pragma unroll
    for (int off = 1; off < 32; off <<= 1) {
        int y = __shfl_up_sync(0xffffffffu, x, off);
        if (lane >= off) x += y;
    }
    int acc = x - s;
#pragma unroll
    for (int j = 0; j < 4; j++) {
        if (base + j < NBLK_SCAN) g_boff[base + j] = acc;
        acc += c[j];
    }
    if (lane == 31) g_colptr[N_NODES] = x;
}

__global__ void k_scan_c() {
    __shared__ int wsum[8], woff[8];
    int b = blockIdx.x, t = threadIdx.x;
    int base = b * 1024 + t * 4;
    int v[4];
#pragma unroll
    for (int j = 0; j < 4; j++) {
        int idx = base + j;
        v[j] = (idx < N_NODES) ? g_cursor[idx] : 0;
    }
    int s = v[0] + v[1] + v[2] + v[3];
    int lane = t & 31, w = t >> 5;
    int x = s;
#pragma unroll
    for (int off = 1; off < 32; off <<= 1) {
        int y = __shfl_up_sync(0xffffffffu, x, off);
        if (lane >= off) x += y;
    }
    if (lane == 31) wsum[w] = x;
    __syncthreads();
    if (t == 0) { int a = 0; for (int i = 0; i < 8; i++) { woff[i] = a; a += wsum[i]; } }
    __syncthreads();
    int excl = (x - s) + woff[w] + g_boff[b];
#pragma unroll
    for (int j = 0; j < 4; j++) {
        int idx = base + j;
        if (idx < N_NODES) {
            g_colptr[idx] = excl;
            g_csrsrc[excl] = idx;      // self loop
            g_cursor[idx] = excl + 1;
        }
        excl += v[j];
    }
}

__global__ void k_filledges(const void* __restrict__ ebuf) {
    int e = blockIdx.x * blockDim.x + threadIdx.x;
    if (e >= N_EDGES) return;
    int s, d;
    if (g_is64) {
        const long long* p = (const long long*)ebuf;
        s = (int)p[e]; d = (int)p[N_EDGES + e];
    } else {
        const int* p = (const int*)ebuf;
        s = p[e]; d = p[N_EDGES + e];
    }
    int pos = atomicAdd(&g_cursor[d], 1);
    g_csrsrc[pos] = s;
}

// ---------------- fused prep: BN consts + all weight transposes -----------
__global__ void k_prep(const float* __restrict__ W0, const float* __restrict__ Ws,
                       const float* __restrict__ bias, const float* __restrict__ gamma,
                       const float* __restrict__ beta, const float* __restrict__ mean,
                       const float* __restrict__ var) {
    int i = blockIdx.x * blockDim.x + threadIdx.x;
    if (i < 4 * H) {
        float s = gamma[i] * rsqrtf(var[i] + BN_EPS);
        g_bnS[i] = s;
        g_bnT[i] = (bias[i] - mean[i]) * s + beta[i];
        return;
    }
    int i0 = i - 4 * H;
    if (i0 < 104 * 48) {                     // layer 0: [104][48] <- W0[33][100]
        int n = i0 / 48, k = i0 % 48;
        g_Wh[i0] = (n < H && k < K0) ? __float2half(W0[k * H + n]) : __float2half(0.f);
        return;
    }
    int i1 = i0 - 104 * 48;
    if (i1 < 3 * WSL) {                      // layers 1-3: [104][112] <- Ws[l][100][100]
        int l = i1 / WSL, r = i1 % WSL;
        int n = r / 112, k = r % 112;
        g_Wh[WSL * (l + 1) + r] = (n < H && k < H)
            ? __float2half(Ws[l * H * H + k * H + n]) : __float2half(0.f);
    }
}

// ---------------- layer-0 aggregate (fused prescale): x -> g_hx fp16 -------
// warp per node; lane L accumulates channel L (ch 32 on lane 0)
__global__ void k_agg0(const float* __restrict__ x) {
    int gwarp = (blockIdx.x * blockDim.x + threadIdx.x) >> 5;
    int lane = threadIdx.x & 31;
    if (gwarp >= N_NODES) return;
    int n = gwarp;
    int beg = g_colptr[n], end = g_colptr[n + 1];
    float a = 0.f, a32 = 0.f;
    for (int i = beg; i < end; i++) {
        int s = g_csrsrc[i];                 // broadcast
        float ds = g_dis[s];                 // broadcast
        a = fmaf(ds, x[s * K0 + lane], a);
        if (lane == 0) a32 = fmaf(ds, x[s * K0 + 32], a32);
    }
    float dn = g_dis[n];
    g_hx[n * K0P + lane] = __float2half(a * dn);
    if (lane == 0) g_hx[n * K0P + 32] = __float2half(a32 * dn);
    else if (lane < 4) g_hx[n * K0P + 32 + lane] = __float2half(0.f);
}

// ---------------- tensor-core GEMM v2: BM=128, 8 warps, dynamic smem -------
// MODE 0: A=g_hx [N,36] -> g_h fp16, epi = BN(layer0)+ReLU
// MODE 1: A=g_h  [N,100] -> g_Y fp16, epi = *dis[row]
template <int KPAD, int KA, int MODE>
__global__ void __launch_bounds__(256) k_mma(const __half* __restrict__ Wp) {
    constexpr int KS = KPAD + 8;
    constexpr int C2 = KA / 2;
    constexpr int P2 = (KPAD - KA) / 2;
    extern __shared__ __half smem[];
    __half* As = smem;                 // [128][KS]
    __half* Bs = smem + 128 * KS;      // [104][KS]
    int row0 = blockIdx.x * 128;
    int tid = threadIdx.x;

    const __half* Asrc = (MODE == 0) ? g_hx : g_h;
    const __half2 z2 = __float2half2_rn(0.f);
    for (int i = tid; i < 128 * C2; i += 256) {
        int r = i / C2, c2 = i % C2;
        int gr = row0 + r;
        __half2 v = (gr < N_NODES) ? ((const __half2*)Asrc)[gr * C2 + c2] : z2;
        *(__half2*)&As[r * KS + c2 * 2] = v;
    }
    for (int i = tid; i < 128 * P2; i += 256) {
        int r = i / P2, j = i % P2;
        *(__half2*)&As[r * KS + KA + j * 2] = z2;
    }
    for (int i = tid; i < 104 * (KPAD / 2); i += 256) {
        int nn = i / (KPAD / 2), c2 = i % (KPAD / 2);
        __half2 v = ((const __half2*)Wp)[i];
        *(__half2*)&Bs[nn * KS + c2 * 2] = v;
    }
    __syncthreads();

    int warp = tid >> 5, lane = tid & 31;
    int g = lane >> 2, t = lane & 3;
    int r0 = warp * 16;
    float acc[13][4];
#pragma unroll
    for (int j = 0; j < 13; j++)
#pragma unroll
        for (int c = 0; c < 4; c++) acc[j][c] = 0.f;

#pragma unroll
    for (int ks = 0; ks < KPAD / 16; ks++) {
        int kb = ks * 16 + t * 2;
        unsigned a0 = *(unsigned*)&As[(r0 + g) * KS + kb];
        unsigned a1 = *(unsigned*)&As[(r0 + g + 8) * KS + kb];
        unsigned a2 = *(unsigned*)&As[(r0 + g) * KS + kb + 8];
        unsigned a3 = *(unsigned*)&As[(r0 + g + 8) * KS + kb + 8];
#pragma unroll
        for (int j = 0; j < 13; j++) {
            int nr = j * 8 + g;
            unsigned b0 = *(unsigned*)&Bs[nr * KS + kb];
            unsigned b1 = *(unsigned*)&Bs[nr * KS + kb + 8];
            asm volatile(
                "mma.sync.aligned.m16n8k16.row.col.f32.f16.f16.f32 "
                "{%0,%1,%2,%3}, {%4,%5,%6,%7}, {%8,%9}, {%0,%1,%2,%3};"
                : "+f"(acc[j][0]), "+f"(acc[j][1]), "+f"(acc[j][2]), "+f"(acc[j][3])
                : "r"(a0), "r"(a1), "r"(a2), "r"(a3), "r"(b0), "r"(b1));
        }
    }

    int gr0 = row0 + r0 + g;
    int gr1 = gr0 + 8;
    if (MODE == 0) {
#pragma unroll
        for (int j = 0; j < 13; j++) {
            int c = j * 8 + t * 2;
            if (c >= H) continue;
            float Sx = g_bnS[c], Sy = g_bnS[c + 1];
            float Tx = g_bnT[c], Ty = g_bnT[c + 1];
            if (gr0 < N_NODES) {
                float ox = fmaxf(fmaf(acc[j][0], Sx, Tx), 0.f);
                float oy = fmaxf(fmaf(acc[j][1], Sy, Ty), 0.f);
                __half2 hv = __floats2half2_rn(ox, oy);
                *(__half2*)&g_h[gr0 * H + c] = hv;
            }
            if (gr1 < N_NODES) {
                float ox = fmaxf(fmaf(acc[j][2], Sx, Tx), 0.f);
                float oy = fmaxf(fmaf(acc[j][3], Sy, Ty), 0.f);
                __half2 hv = __floats2half2_rn(ox, oy);
                *(__half2*)&g_h[gr1 * H + c] = hv;
            }
        }
    } else {
        float d0 = (gr0 < N_NODES) ? g_dis[gr0] : 0.f;
        float d1 = (gr1 < N_NODES) ? g_dis[gr1] : 0.f;
#pragma unroll
        for (int j = 0; j < 13; j++) {
            int c = j * 8 + t * 2;
            if (c >= H) continue;
            if (gr0 < N_NODES) {
                __half2 hv = __floats2half2_rn(acc[j][0] * d0, acc[j][1] * d0);
                *(__half2*)&g_Y[gr0 * H + c] = hv;
            }
            if (gr1 < N_NODES) {
                __half2 hv = __floats2half2_rn(acc[j][2] * d1, acc[j][3] * d1);
                *(__half2*)&g_Y[gr1 * H + c] = hv;
            }
        }
    }
}

// ---------------- aggregation: g_Y(fp16) -> g_h(fp16)  [LAST: fused pool] --
template <int LAST>
__global__ void k_agg(int layer, int relu, const float* __restrict__ hW) {
    int gwarp = (blockIdx.x * blockDim.x + threadIdx.x) >> 5;
    int lane = threadIdx.x & 31;
    if (gwarp >= N_NODES) return;
    int n = gwarp;
    float ox = 0.f, oy = 0.f, oz = 0.f, ow = 0.f;
    if (lane < H4) {
        int beg = g_colptr[n], end = g_colptr[n + 1];
        const uint2* Y2 = (const uint2*)g_Y;
        float a0x=0.f,a0y=0.f,a0z=0.f,a0w=0.f;
        float a1x=0.f,a1y=0.f,a1z=0.f,a1w=0.f;
        float a2x=0.f,a2y=0.f,a2z=0.f,a2w=0.f;
        float a3x=0.f,a3y=0.f,a3z=0.f,a3w=0.f;
        int i = beg;
        for (; i + 3 < end; i += 4) {
            int s0 = g_csrsrc[i], s1 = g_csrsrc[i+1], s2 = g_csrsrc[i+2], s3 = g_csrsrc[i+3];
            uint2 u0 = Y2[s0 * H4 + lane];
            uint2 u1 = Y2[s1 * H4 + lane];
            uint2 u2 = Y2[s2 * H4 + lane];
            uint2 u3 = Y2[s3 * H4 + lane];
            float2 p;
            p = __half22float2(*(__half2*)&u0.x); a0x += p.x; a0y += p.y;
            p = __half22float2(*(__half2*)&u0.y); a0z += p.x; a0w += p.y;
            p = __half22float2(*(__half2*)&u1.x); a1x += p.x; a1y += p.y;
            p = __half22float2(*(__half2*)&u1.y); a1z += p.x; a1w += p.y;
            p = __half22float2(*(__half2*)&u2.x); a2x += p.x; a2y += p.y;
            p = __half22float2(*(__half2*)&u2.y); a2z += p.x; a2w += p.y;
            p = __half22float2(*(__half2*)&u3.x); a3x += p.x; a3y += p.y;
            p = __half22float2(*(__half2*)&u3.y); a3z += p.x; a3w += p.y;
        }
        for (; i < end; i++) {
            int s0 = g_csrsrc[i];
            uint2 u0 = Y2[s0 * H4 + lane];
            float2 p;
            p = __half22float2(*(__half2*)&u0.x); a0x += p.x; a0y += p.y;
            p = __half22float2(*(__half2*)&u0.y); a0z += p.x; a0w += p.y;
        }
        float ax = (a0x + a1x) + (a2x + a3x);
        float ay = (a0y + a1y) + (a2y + a3y);
        float az = (a0z + a1z) + (a2z + a3z);
        float aw = (a0w + a1w) + (a2w + a3w);
        float d = g_dis[n];
        int c = layer * H + lane * 4;
        float4 S = *(const float4*)&g_bnS[c];
        float4 T = *(const float4*)&g_bnT[c];
        ox = fmaf(ax * d, S.x, T.x);
        oy = fmaf(ay * d, S.y, T.y);
        oz = fmaf(az * d, S.z, T.z);
        ow = fmaf(aw * d, S.w, T.w);
        if (relu) {
            ox = fmaxf(ox, 0.f); oy = fmaxf(oy, 0.f);
            oz = fmaxf(oz, 0.f); ow = fmaxf(ow, 0.f);
        }
    }
    if (LAST == 0) {
        if (lane < H4) {
            __half2 h0 = __floats2half2_rn(ox, oy);
            __half2 h1 = __floats2half2_rn(oz, ow);
            uint2 u; u.x = *(unsigned*)&h0; u.y = *(unsigned*)&h1;
            *(uint2*)&g_h[n * H + lane * 4] = u;
        }
    } else {
        float s = 0.f;
        if (lane < H4) {
            float4 w4 = ((const float4*)hW)[lane];
            s = ox * w4.x + oy * w4.y + oz * w4.z + ow * w4.w;
        }
#pragma unroll
        for (int off = 16; off > 0; off >>= 1)
            s += __shfl_down_sync(0xffffffffu, s, off);
        if (lane == 0) atomicAdd(&g_gsum[g_batch[n]], s);
    }
}

// ---------------- finish: bias + LeakyReLU ----------------
__global__ void k_finish(const float* __restrict__ hb, float* __restrict__ out) {
    int g = blockIdx.x * blockDim.x + threadIdx.x;
    if (g >= N_GRAPHSX) return;
    float o = g_gsum[g] + hb[0];
    out[g] = (o >= 0.f) ? o : 0.1f * o;
}

// ---------------- launch ----------------
extern "C" void kernel_launch(void* const* d_in, const int* in_sizes, int n_in,
                              void* d_out, int out_size) {
    const float* x      = (const float*)d_in[0];
    const void*  ei     = d_in[1];
    const void*  batch  = d_in[2];
    const float* W0     = (const float*)d_in[3];
    const float* Ws     = (const float*)d_in[4];
    const float* biases = (const float*)d_in[5];
    const float* gamma  = (const float*)d_in[6];
    const float* beta   = (const float*)d_in[7];
    const float* mean   = (const float*)d_in[8];
    const float* var    = (const float*)d_in[9];
    const float* headW  = (const float*)d_in[10];
    const float* headb  = (const float*)d_in[11];
    float* out = (float*)d_out;

    static int attr_done = 0;
    const int smem_big   = (128 + 104) * (112 + 8) * 2;  // 55680
    const int smem_small = (128 + 104) * (48 + 8) * 2;   // 25984
    if (!attr_done) {
        cudaFuncSetAttribute(k_mma<112, 100, 1>, cudaFuncAttributeMaxDynamicSharedMemorySize, smem_big);
        cudaFuncSetAttribute(k_mma<48, 36, 0>,   cudaFuncAttributeMaxDynamicSharedMemorySize, smem_small);
        attr_done = 1;
    }

    // device pointer to weight staging (device-global address, host-computable)
    __half* whp = nullptr;
    cudaGetSymbolAddress((void**)&whp, g_Wh);

    k_init<<<(N_NODES + 255) / 256, 256>>>((const unsigned*)ei);
    k_count<<<(N_EDGES + 255) / 256, 256>>>(ei);
    k_gptr<<<(N_NODES + 255) / 256, 256>>>(batch);
    k_scan_a<<<NBLK_SCAN, 256>>>();
    k_scan_b<<<1, 32>>>();
    k_scan_c<<<NBLK_SCAN, 256>>>();
    k_filledges<<<(N_EDGES + 255) / 256, 256>>>(ei);
    k_prep<<<(4 * H + 104 * 48 + 3 * WSL + 255) / 256, 256>>>(W0, Ws, biases, gamma, beta, mean, var);

    int mma_blocks = (N_NODES + 127) / 128;
    int agg_blocks = (N_NODES * 32 + 255) / 256;

    // layer 0: fused prescale+aggregate -> MMA (BN0+ReLU)
    k_agg0<<<agg_blocks, 256>>>(x);
    k_mma<48, 36, 0><<<mma_blocks, 256, smem_small>>>(whp);
    // layers 1..3
    for (int l = 1; l < 4; l++) {
        k_mma<112, 100, 1><<<mma_blocks, 256, smem_big>>>(whp + l * WSL);
        if (l < 3) k_agg<0><<<agg_blocks, 256>>>(l, 1, headW);
        else       k_agg<1><<<agg_blocks, 256>>>(l, 0, headW);
    }

    k_finish<<<(N_GRAPHSX + 255) / 256, 256>>>(headb, out);
}

// round 16
// speedup vs baseline: 1.1897x; 1.0634x over previous
#include <cuda_runtime.h>
#include <cuda_fp16.h>

#define N_NODES   100000
#define N_EDGES   1600000
#define N_TOT     1700000
#define N_GRAPHSX 2048
#define H         100
#define H4        25
#define K0        33
#define K0P       36
#define BN_EPS    1e-5f
#define NBLK_SCAN 98
#define WSL       (104 * 112)   // weight staging slice

#define GDC_WAIT()   asm volatile("griddepcontrol.wait;" ::: "memory")
#define GDC_LAUNCH() asm volatile("griddepcontrol.launch_dependents;" ::: "memory")

// ---------------- scratch ----------------
__device__ __align__(16) __half g_hx[N_NODES * K0P];    // aggregated x (fp16)
__device__ __align__(16) __half g_h[N_NODES * H];       // h (fp16)
__device__ __align__(16) __half g_Y[N_NODES * H];       // Y = dis*(h@W) (fp16)
__device__ __align__(16) __half g_Wh[4 * WSL];          // transposed fp16 weights
__device__ __align__(16) float  g_bnS[4 * H];
__device__ __align__(16) float  g_bnT[4 * H];
__device__ float g_gsum[N_GRAPHSX];
__device__ float g_dis[N_NODES];
__device__ int   g_colptr[N_NODES + 1];
__device__ int   g_cursor[N_NODES];
__device__ int   g_csrsrc[N_TOT];
__device__ int   g_batch[N_NODES];
__device__ int   g_bsum[128];
__device__ int   g_boff[128];
__device__ int   g_is64;

// ---------------- init + probe ----------------
__global__ void k_init(const unsigned* __restrict__ ebuf) {
    int i = blockIdx.x * blockDim.x + threadIdx.x;
    if (i < N_NODES) g_cursor[i] = 1;
    if (i < N_GRAPHSX) g_gsum[i] = 0.f;
    if (i == 0) {
        int all0 = 1;
        for (int j = 1; j < 128; j += 2) all0 &= (ebuf[j] == 0u);
        g_is64 = all0;
    }
}

__global__ void k_count(const void* __restrict__ ebuf) {
    int e = blockIdx.x * blockDim.x + threadIdx.x;
    if (e >= N_EDGES) return;
    int d = g_is64 ? (int)((const long long*)ebuf)[N_EDGES + e]
                   : ((const int*)ebuf)[N_EDGES + e];
    atomicAdd(&g_cursor[d], 1);
}

__global__ void k_gptr(const void* __restrict__ bbuf) {
    int i = blockIdx.x * blockDim.x + threadIdx.x;
    if (i >= N_NODES) return;
    int b = g_is64 ? (int)((const long long*)bbuf)[i] : ((const int*)bbuf)[i];
    g_batch[i] = b;
}

// ---------------- scans ----------------
__global__ void k_scan_a() {
    __shared__ int red[256];
    int b = blockIdx.x, t = threadIdx.x;
    int base = b * 1024 + t * 4;
    int s = 0;
#pragma unroll
    for (int j = 0; j < 4; j++) {
        int idx = base + j;
        if (idx < N_NODES) {
            int c = g_cursor[idx];
            s += c;
            g_dis[idx] = rsqrtf((float)c);
        }
    }
    red[t] = s; __syncthreads();
    for (int off = 128; off > 0; off >>= 1) {
        if (t < off) red[t] += red[t + off];
        __syncthreads();
    }
    if (t == 0) g_bsum[b] = red[0];
}

__global__ void k_scan_b() {
    int lane = threadIdx.x;
    int base = lane * 4;
    int c[4]; int s = 0;
#pragma unroll
    for (int j = 0; j < 4; j++) {
        c[j] = (base + j < NBLK_SCAN) ? g_bsum[base + j] : 0;
        s += c[j];
    }
    int x = s;
#pragma unroll
    for (int off = 1; off < 32; off <<= 1) {
        int y = __shfl_up_sync(0xffffffffu, x, off);
        if (lane >= off) x += y;
    }
    int acc = x - s;
#pragma unroll
    for (int j = 0; j < 4; j++) {
        if (base + j < NBLK_SCAN) g_boff[base + j] = acc;
        acc += c[j];
    }
    if (lane == 31) g_colptr[N_NODES] = x;
}

__global__ void k_scan_c() {
    __shared__ int wsum[8], woff[8];
    int b = blockIdx.x, t = threadIdx.x;
    int base = b * 1024 + t * 4;
    int v[4];
#pragma unroll
    for (int j = 0; j < 4; j++) {
        int idx = base + j;
        v[j] = (idx < N_NODES) ? g_cursor[idx] : 0;
    }
    int s = v[0] + v[1] + v[2] + v[3];
    int lane = t & 31, w = t >> 5;
    int x = s;
#pragma unroll
    for (int off = 1; off < 32; off <<= 1) {
        int y = __shfl_up_sync(0xffffffffu, x, off);
        if (lane >= off) x += y;
    }
    if (lane == 31) wsum[w] = x;
    __syncthreads();
    if (t == 0) { int a = 0; for (int i = 0; i < 8; i++) { woff[i] = a; a += wsum[i]; } }
    __syncthreads();
    int excl = (x - s) + woff[w] + g_boff[b];
#pragma unroll
    for (int j = 0; j < 4; j++) {
        int idx = base + j;
        if (idx < N_NODES) {
            g_colptr[idx] = excl;
            g_csrsrc[excl] = idx;      // self loop
            g_cursor[idx] = excl + 1;
        }
        excl += v[j];
    }
}

__global__ void k_filledges(const void* __restrict__ ebuf) {
    GDC_WAIT();
    GDC_LAUNCH();
    int e = blockIdx.x * blockDim.x + threadIdx.x;
    if (e >= N_EDGES) return;
    int s, d;
    if (g_is64) {
        const long long* p = (const long long*)ebuf;
        s = (int)p[e]; d = (int)p[N_EDGES + e];
    } else {
        const int* p = (const int*)ebuf;
        s = p[e]; d = p[N_EDGES + e];
    }
    int pos = atomicAdd(&g_cursor[d], 1);
    g_csrsrc[pos] = s;
}

// ---------------- fused prep: BN consts + all weight transposes -----------
__global__ void k_prep(const float* __restrict__ W0, const float* __restrict__ Ws,
                       const float* __restrict__ bias, const float* __restrict__ gamma,
                       const float* __restrict__ beta, const float* __restrict__ mean,
                       const float* __restrict__ var) {
    GDC_WAIT();
    GDC_LAUNCH();
    int i = blockIdx.x * blockDim.x + threadIdx.x;
    if (i < 4 * H) {
        float s = gamma[i] * rsqrtf(var[i] + BN_EPS);
        g_bnS[i] = s;
        g_bnT[i] = (bias[i] - mean[i]) * s + beta[i];
        return;
    }
    int i0 = i - 4 * H;
    if (i0 < 104 * 48) {                     // layer 0: [104][48] <- W0[33][100]
        int n = i0 / 48, k = i0 % 48;
        g_Wh[i0] = (n < H && k < K0) ? __float2half(W0[k * H + n]) : __float2half(0.f);
        return;
    }
    int i1 = i0 - 104 * 48;
    if (i1 < 3 * WSL) {                      // layers 1-3: [104][112] <- Ws[l][100][100]
        int l = i1 / WSL, r = i1 % WSL;
        int n = r / 112, k = r % 112;
        g_Wh[WSL * (l + 1) + r] = (n < H && k < H)
            ? __float2half(Ws[l * H * H + k * H + n]) : __float2half(0.f);
    }
}

// ---------------- layer-0 aggregate (fused prescale): x -> g_hx fp16 -------
__global__ void k_agg0(const float* __restrict__ x) {
    GDC_WAIT();
    GDC_LAUNCH();
    int gwarp = (blockIdx.x * blockDim.x + threadIdx.x) >> 5;
    int lane = threadIdx.x & 31;
    if (gwarp >= N_NODES) return;
    int n = gwarp;
    int beg = g_colptr[n], end = g_colptr[n + 1];
    float a = 0.f, a32 = 0.f;
    for (int i = beg; i < end; i++) {
        int s = g_csrsrc[i];                 // broadcast
        float ds = g_dis[s];                 // broadcast
        a = fmaf(ds, x[s * K0 + lane], a);
        if (lane == 0) a32 = fmaf(ds, x[s * K0 + 32], a32);
    }
    float dn = g_dis[n];
    g_hx[n * K0P + lane] = __float2half(a * dn);
    if (lane == 0) g_hx[n * K0P + 32] = __float2half(a32 * dn);
    else if (lane < 4) g_hx[n * K0P + 32 + lane] = __float2half(0.f);
}

// ---------------- tensor-core GEMM: BM=128, 8 warps, dynamic smem ----------
// PDL: B-tile fill (weights, >=2 kernels upstream) runs BEFORE griddep wait,
// overlapping the predecessor's tail; A-tile fill after wait.
// MODE 0: A=g_hx [N,36] -> g_h fp16, epi = BN(layer0)+ReLU
// MODE 1: A=g_h  [N,100] -> g_Y fp16, epi = *dis[row]
template <int KPAD, int KA, int MODE>
__global__ void __launch_bounds__(256) k_mma(const __half* __restrict__ Wp) {
    constexpr int KS = KPAD + 8;
    constexpr int C2 = KA / 2;
    constexpr int P2 = (KPAD - KA) / 2;
    extern __shared__ __half smem[];
    __half* As = smem;                 // [128][KS]
    __half* Bs = smem + 128 * KS;      // [104][KS]
    int row0 = blockIdx.x * 128;
    int tid = threadIdx.x;
    const __half2 z2 = __float2half2_rn(0.f);

    // preamble (safe: weights written by k_prep, >=2 kernels upstream)
    for (int i = tid; i < 104 * (KPAD / 2); i += 256) {
        int nn = i / (KPAD / 2), c2 = i % (KPAD / 2);
        __half2 v = ((const __half2*)Wp)[i];
        *(__half2*)&Bs[nn * KS + c2 * 2] = v;
    }
    for (int i = tid; i < 128 * P2; i += 256) {
        int r = i / P2, j = i % P2;
        *(__half2*)&As[r * KS + KA + j * 2] = z2;
    }

    GDC_WAIT();
    GDC_LAUNCH();

    const __half* Asrc = (MODE == 0) ? g_hx : g_h;
    for (int i = tid; i < 128 * C2; i += 256) {
        int r = i / C2, c2 = i % C2;
        int gr = row0 + r;
        __half2 v = (gr < N_NODES) ? ((const __half2*)Asrc)[gr * C2 + c2] : z2;
        *(__half2*)&As[r * KS + c2 * 2] = v;
    }
    __syncthreads();

    int warp = tid >> 5, lane = tid & 31;
    int g = lane >> 2, t = lane & 3;
    int r0 = warp * 16;
    float acc[13][4];
#pragma unroll
    for (int j = 0; j < 13; j++)
#pragma unroll
        for (int c = 0; c < 4; c++) acc[j][c] = 0.f;

#pragma unroll
    for (int ks = 0; ks < KPAD / 16; ks++) {
        int kb = ks * 16 + t * 2;
        unsigned a0 = *(unsigned*)&As[(r0 + g) * KS + kb];
        unsigned a1 = *(unsigned*)&As[(r0 + g + 8) * KS + kb];
        unsigned a2 = *(unsigned*)&As[(r0 + g) * KS + kb + 8];
        unsigned a3 = *(unsigned*)&As[(r0 + g + 8) * KS + kb + 8];
#pragma unroll
        for (int j = 0; j < 13; j++) {
            int nr = j * 8 + g;
            unsigned b0 = *(unsigned*)&Bs[nr * KS + kb];
            unsigned b1 = *(unsigned*)&Bs[nr * KS + kb + 8];
            asm volatile(
                "mma.sync.aligned.m16n8k16.row.col.f32.f16.f16.f32 "
                "{%0,%1,%2,%3}, {%4,%5,%6,%7}, {%8,%9}, {%0,%1,%2,%3};"
                : "+f"(acc[j][0]), "+f"(acc[j][1]), "+f"(acc[j][2]), "+f"(acc[j][3])
                : "r"(a0), "r"(a1), "r"(a2), "r"(a3), "r"(b0), "r"(b1));
        }
    }

    int gr0 = row0 + r0 + g;
    int gr1 = gr0 + 8;
    if (MODE == 0) {
#pragma unroll
        for (int j = 0; j < 13; j++) {
            int c = j * 8 + t * 2;
            if (c >= H) continue;
            float Sx = g_bnS[c], Sy = g_bnS[c + 1];
            float Tx = g_bnT[c], Ty = g_bnT[c + 1];
            if (gr0 < N_NODES) {
                float ox = fmaxf(fmaf(acc[j][0], Sx, Tx), 0.f);
                float oy = fmaxf(fmaf(acc[j][1], Sy, Ty), 0.f);
                __half2 hv = __floats2half2_rn(ox, oy);
                *(__half2*)&g_h[gr0 * H + c] = hv;
            }
            if (gr1 < N_NODES) {
                float ox = fmaxf(fmaf(acc[j][2], Sx, Tx), 0.f);
                float oy = fmaxf(fmaf(acc[j][3], Sy, Ty), 0.f);
                __half2 hv = __floats2half2_rn(ox, oy);
                *(__half2*)&g_h[gr1 * H + c] = hv;
            }
        }
    } else {
        float d0 = (gr0 < N_NODES) ? g_dis[gr0] : 0.f;
        float d1 = (gr1 < N_NODES) ? g_dis[gr1] : 0.f;
#pragma unroll
        for (int j = 0; j < 13; j++) {
            int c = j * 8 + t * 2;
            if (c >= H) continue;
            if (gr0 < N_NODES) {
                __half2 hv = __floats2half2_rn(acc[j][0] * d0, acc[j][1] * d0);
                *(__half2*)&g_Y[gr0 * H + c] = hv;
            }
            if (gr1 < N_NODES) {
                __half2 hv = __floats2half2_rn(acc[j][2] * d1, acc[j][3] * d1);
                *(__half2*)&g_Y[gr1 * H + c] = hv;
            }
        }
    }
}

// ---------------- aggregation: g_Y(fp16) -> g_h(fp16)  [LAST: fused pool] --
template <int LAST>
__global__ void k_agg(int layer, int relu, const float* __restrict__ hW) {
    GDC_WAIT();
    GDC_LAUNCH();
    int gwarp = (blockIdx.x * blockDim.x + threadIdx.x) >> 5;
    int lane = threadIdx.x & 31;
    if (gwarp >= N_NODES) return;
    int n = gwarp;
    float ox = 0.f, oy = 0.f, oz = 0.f, ow = 0.f;
    if (lane < H4) {
        int beg = g_colptr[n], end = g_colptr[n + 1];
        const uint2* Y2 = (const uint2*)g_Y;
        float a0x=0.f,a0y=0.f,a0z=0.f,a0w=0.f;
        float a1x=0.f,a1y=0.f,a1z=0.f,a1w=0.f;
        float a2x=0.f,a2y=0.f,a2z=0.f,a2w=0.f;
        float a3x=0.f,a3y=0.f,a3z=0.f,a3w=0.f;
        int i = beg;
        for (; i + 3 < end; i += 4) {
            int s0 = g_csrsrc[i], s1 = g_csrsrc[i+1], s2 = g_csrsrc[i+2], s3 = g_csrsrc[i+3];
            uint2 u0 = Y2[s0 * H4 + lane];
            uint2 u1 = Y2[s1 * H4 + lane];
            uint2 u2 = Y2[s2 * H4 + lane];
            uint2 u3 = Y2[s3 * H4 + lane];
            float2 p;
            p = __half22float2(*(__half2*)&u0.x); a0x += p.x; a0y += p.y;
            p = __half22float2(*(__half2*)&u0.y); a0z += p.x; a0w += p.y;
            p = __half22float2(*(__half2*)&u1.x); a1x += p.x; a1y += p.y;
            p = __half22float2(*(__half2*)&u1.y); a1z += p.x; a1w += p.y;
            p = __half22float2(*(__half2*)&u2.x); a2x += p.x; a2y += p.y;
            p = __half22float2(*(__half2*)&u2.y); a2z += p.x; a2w += p.y;
            p = __half22float2(*(__half2*)&u3.x); a3x += p.x; a3y += p.y;
            p = __half22float2(*(__half2*)&u3.y); a3z += p.x; a3w += p.y;
        }
        for (; i < end; i++) {
            int s0 = g_csrsrc[i];
            uint2 u0 = Y2[s0 * H4 + lane];
            float2 p;
            p = __half22float2(*(__half2*)&u0.x); a0x += p.x; a0y += p.y;
            p = __half22float2(*(__half2*)&u0.y); a0z += p.x; a0w += p.y;
        }
        float ax = (a0x + a1x) + (a2x + a3x);
        float ay = (a0y + a1y) + (a2y + a3y);
        float az = (a0z + a1z) + (a2z + a3z);
        float aw = (a0w + a1w) + (a2w + a3w);
        float d = g_dis[n];
        int c = layer * H + lane * 4;
        float4 S = *(const float4*)&g_bnS[c];
        float4 T = *(const float4*)&g_bnT[c];
        ox = fmaf(ax * d, S.x, T.x);
        oy = fmaf(ay * d, S.y, T.y);
        oz = fmaf(az * d, S.z, T.z);
        ow = fmaf(aw * d, S.w, T.w);
        if (relu) {
            ox = fmaxf(ox, 0.f); oy = fmaxf(oy, 0.f);
            oz = fmaxf(oz, 0.f); ow = fmaxf(ow, 0.f);
        }
    }
    if (LAST == 0) {
        if (lane < H4) {
            __half2 h0 = __floats2half2_rn(ox, oy);
            __half2 h1 = __floats2half2_rn(oz, ow);
            uint2 u; u.x = *(unsigned*)&h0; u.y = *(unsigned*)&h1;
            *(uint2*)&g_h[n * H + lane * 4] = u;
        }
    } else {
        float s = 0.f;
        if (lane < H4) {
            float4 w4 = ((const float4*)hW)[lane];
            s = ox * w4.x + oy * w4.y + oz * w4.z + ow * w4.w;
        }
#pragma unroll
        for (int off = 16; off > 0; off >>= 1)
            s += __shfl_down_sync(0xffffffffu, s, off);
        if (lane == 0) atomicAdd(&g_gsum[g_batch[n]], s);
    }
}

// ---------------- finish: bias + LeakyReLU ----------------
__global__ void k_finish(const float* __restrict__ hb, float* __restrict__ out) {
    GDC_WAIT();
    int g = blockIdx.x * blockDim.x + threadIdx.x;
    if (g >= N_GRAPHSX) return;
    float o = g_gsum[g] + hb[0];
    out[g] = (o >= 0.f) ? o : 0.1f * o;
}

// ---------------- PDL launch helper ----------------
template <typename... Args>
static void pdl_launch(void (*fn)(Args...), dim3 grid, dim3 block, size_t smem, Args... args) {
    void* pargs[sizeof...(Args)] = { (void*)&args... };
    cudaLaunchConfig_t cfg = {};
    cfg.gridDim = grid;
    cfg.blockDim = block;
    cfg.dynamicSmemBytes = smem;
    cfg.stream = 0;
    cudaLaunchAttribute attr;
    attr.id = cudaLaunchAttributeProgrammaticStreamSerialization;
    attr.val.programmaticStreamSerializationAllowed = 1;
    cfg.attrs = &attr;
    cfg.numAttrs = 1;
    cudaLaunchKernelExC(&cfg, (const void*)fn, pargs);
}

// ---------------- launch ----------------
extern "C" void kernel_launch(void* const* d_in, const int* in_sizes, int n_in,
                              void* d_out, int out_size) {
    const float* x      = (const float*)d_in[0];
    const void*  ei     = d_in[1];
    const void*  batch  = d_in[2];
    const float* W0     = (const float*)d_in[3];
    const float* Ws     = (const float*)d_in[4];
    const float* biases = (const float*)d_in[5];
    const float* gamma  = (const float*)d_in[6];
    const float* beta   = (const float*)d_in[7];
    const float* mean   = (const float*)d_in[8];
    const float* var    = (const float*)d_in[9];
    const float* headW  = (const float*)d_in[10];
    const float* headb  = (const float*)d_in[11];
    float* out = (float*)d_out;

    const int smem_big   = (128 + 104) * (112 + 8) * 2;  // 55680
    const int smem_small = (128 + 104) * (48 + 8) * 2;   // 25984
    cudaFuncSetAttribute(k_mma<112, 100, 1>, cudaFuncAttributeMaxDynamicSharedMemorySize, smem_big);
    cudaFuncSetAttribute(k_mma<48, 36, 0>,   cudaFuncAttributeMaxDynamicSharedMemorySize, smem_small);

    __half* whp = nullptr;
    cudaGetSymbolAddress((void**)&whp, g_Wh);

    int mma_blocks = (N_NODES + 127) / 128;
    int agg_blocks = (N_NODES * 32 + 255) / 256;

    // CSR build (normal launches; dependency chain needs full global syncs)
    k_init<<<(N_NODES + 255) / 256, 256>>>((const unsigned*)ei);
    k_count<<<(N_EDGES + 255) / 256, 256>>>(ei);
    k_gptr<<<(N_NODES + 255) / 256, 256>>>(batch);
    k_scan_a<<<NBLK_SCAN, 256>>>();
    k_scan_b<<<1, 32>>>();
    k_scan_c<<<NBLK_SCAN, 256>>>();

    // PDL chain from here on — each kernel's launch/preamble overlaps the
    // predecessor's tail; griddepcontrol.wait guards dependent data.
    pdl_launch(k_filledges, dim3((N_EDGES + 255) / 256), dim3(256), (size_t)0,
               (const void*)ei);
    pdl_launch(k_prep, dim3((4 * H + 104 * 48 + 3 * WSL + 255) / 256), dim3(256), (size_t)0,
               (const float*)W0, (const float*)Ws, (const float*)biases,
               (const float*)gamma, (const float*)beta, (const float*)mean,
               (const float*)var);
    pdl_launch(k_agg0, dim3(agg_blocks), dim3(256), (size_t)0, (const float*)x);
    pdl_launch(k_mma<48, 36, 0>, dim3(mma_blocks), dim3(256), (size_t)smem_small,
               (const __half*)whp);
    for (int l = 1; l < 4; l++) {
        pdl_launch(k_mma<112, 100, 1>, dim3(mma_blocks), dim3(256), (size_t)smem_big,
                   (const __half*)(whp + l * WSL));
        if (l < 3) pdl_launch(k_agg<0>, dim3(agg_blocks), dim3(256), (size_t)0,
                              (int)l, (int)1, (const float*)headW);
        else       pdl_launch(k_agg<1>, dim3(agg_blocks), dim3(256), (size_t)0,
                              (int)l, (int)0, (const float*)headW);
    }
    pdl_launch(k_finish, dim3((N_GRAPHSX + 255) / 256), dim3(256), (size_t)0,
               (const float*)headb, (float*)out);
}

// round 17
// speedup vs baseline: 1.2093x; 1.0165x over previous
#include <cuda_runtime.h>
#include <cuda_fp16.h>

#define N_NODES   100000
#define N_EDGES   1600000
#define N_TOT     1700000
#define N_GRAPHSX 2048
#define H         100
#define H4        25
#define K0        33
#define K0P       36
#define BN_EPS    1e-5f
#define NBLK_SCAN 98
#define WSL       (104 * 112)   // weight staging slice

#define GDC_WAIT()   asm volatile("griddepcontrol.wait;" ::: "memory")
#define GDC_LAUNCH() asm volatile("griddepcontrol.launch_dependents;" ::: "memory")

// ---------------- scratch ----------------
__device__ __align__(16) __half g_hx[N_NODES * K0P];    // aggregated x (fp16)
__device__ __align__(16) __half g_h[N_NODES * H];       // h (fp16)
__device__ __align__(16) __half g_Y[N_NODES * H];       // Y = dis*(h@W) (fp16)
__device__ __align__(16) __half g_Wh[4 * WSL];          // transposed fp16 weights
__device__ __align__(16) float  g_bnS[4 * H];
__device__ __align__(16) float  g_bnT[4 * H];
__device__ float g_gsum[N_GRAPHSX];
__device__ float g_dis[N_NODES];
__device__ int   g_colptr[N_NODES + 1];
__device__ int   g_cursor[N_NODES];
__device__ int   g_csrsrc[N_TOT];
__device__ int   g_batch[N_NODES];
__device__ int   g_bsum[128];
__device__ int   g_boff[128];
__device__ int   g_is64;

// ---------------- init + probe + prep (merged; all input-only work) --------
__global__ void k_init(const unsigned* __restrict__ ebuf,
                       const float* __restrict__ W0, const float* __restrict__ Ws,
                       const float* __restrict__ bias, const float* __restrict__ gamma,
                       const float* __restrict__ beta, const float* __restrict__ mean,
                       const float* __restrict__ var) {
    GDC_WAIT();
    GDC_LAUNCH();
    int i = blockIdx.x * blockDim.x + threadIdx.x;
    if (i < N_NODES) g_cursor[i] = 1;
    if (i < N_GRAPHSX) g_gsum[i] = 0.f;
    if (i == 0) {
        int all0 = 1;
        for (int j = 1; j < 128; j += 2) all0 &= (ebuf[j] == 0u);
        g_is64 = all0;
    }
    // prep: BN constants + weight transposes (independent of graph data)
    if (i < 4 * H) {
        float s = gamma[i] * rsqrtf(var[i] + BN_EPS);
        g_bnS[i] = s;
        g_bnT[i] = (bias[i] - mean[i]) * s + beta[i];
    }
    int i0 = i - 4 * H;
    if (i0 >= 0 && i0 < 104 * 48) {          // layer 0: [104][48] <- W0[33][100]
        int n = i0 / 48, k = i0 % 48;
        g_Wh[i0] = (n < H && k < K0) ? __float2half(W0[k * H + n]) : __float2half(0.f);
    }
    int i1 = i0 - 104 * 48;
    if (i1 >= 0 && i1 < 3 * WSL) {           // layers 1-3: [104][112] <- Ws[l][100][100]
        int l = i1 / WSL, r = i1 % WSL;
        int n = r / 112, k = r % 112;
        g_Wh[WSL * (l + 1) + r] = (n < H && k < H)
            ? __float2half(Ws[l * H * H + k * H + n]) : __float2half(0.f);
    }
}

// degree count + batch conversion (merged)
__global__ void k_count(const void* __restrict__ ebuf, const void* __restrict__ bbuf) {
    GDC_WAIT();
    GDC_LAUNCH();
    int i = blockIdx.x * blockDim.x + threadIdx.x;
    int is64 = g_is64;
    if (i < N_EDGES) {
        int d = is64 ? (int)((const long long*)ebuf)[N_EDGES + i]
                     : ((const int*)ebuf)[N_EDGES + i];
        atomicAdd(&g_cursor[d], 1);
    }
    if (i < N_NODES)
        g_batch[i] = is64 ? (int)((const long long*)bbuf)[i] : ((const int*)bbuf)[i];
}

// ---------------- scans ----------------
__global__ void k_scan_a() {
    GDC_WAIT();
    GDC_LAUNCH();
    __shared__ int red[256];
    int b = blockIdx.x, t = threadIdx.x;
    int base = b * 1024 + t * 4;
    int s = 0;
#pragma unroll
    for (int j = 0; j < 4; j++) {
        int idx = base + j;
        if (idx < N_NODES) {
            int c = g_cursor[idx];
            s += c;
            g_dis[idx] = rsqrtf((float)c);
        }
    }
    red[t] = s; __syncthreads();
    for (int off = 128; off > 0; off >>= 1) {
        if (t < off) red[t] += red[t + off];
        __syncthreads();
    }
    if (t == 0) g_bsum[b] = red[0];
}

__global__ void k_scan_b() {
    GDC_WAIT();
    GDC_LAUNCH();
    int lane = threadIdx.x;
    int base = lane * 4;
    int c[4]; int s = 0;
#pragma unroll
    for (int j = 0; j < 4; j++) {
        c[j] = (base + j < NBLK_SCAN) ? g_bsum[base + j] : 0;
        s += c[j];
    }
    int x = s;
#pragma unroll
    for (int off = 1; off < 32; off <<= 1) {
        int y = __shfl_up_sync(0xffffffffu, x, off);
        if (lane >= off) x += y;
    }
    int acc = x - s;
#pragma unroll
    for (int j = 0; j < 4; j++) {
        if (base + j < NBLK_SCAN) g_boff[base + j] = acc;
        acc += c[j];
    }
    if (lane == 31) g_colptr[N_NODES] = x;
}

__global__ void k_scan_c() {
    GDC_WAIT();
    GDC_LAUNCH();
    __shared__ int wsum[8], woff[8];
    int b = blockIdx.x, t = threadIdx.x;
    int base = b * 1024 + t * 4;
    int v[4];
#pragma unroll
    for (int j = 0; j < 4; j++) {
        int idx = base + j;
        v[j] = (idx < N_NODES) ? g_cursor[idx] : 0;
    }
    int s = v[0] + v[1] + v[2] + v[3];
    int lane = t & 31, w = t >> 5;
    int x = s;
#pragma unroll
    for (int off = 1; off < 32; off <<= 1) {
        int y = __shfl_up_sync(0xffffffffu, x, off);
        if (lane >= off) x += y;
    }
    if (lane == 31) wsum[w] = x;
    __syncthreads();
    if (t == 0) { int a = 0; for (int i = 0; i < 8; i++) { woff[i] = a; a += wsum[i]; } }
    __syncthreads();
    int excl = (x - s) + woff[w] + g_boff[b];
#pragma unroll
    for (int j = 0; j < 4; j++) {
        int idx = base + j;
        if (idx < N_NODES) {
            g_colptr[idx] = excl;
            g_csrsrc[excl] = idx;      // self loop
            g_cursor[idx] = excl + 1;
        }
        excl += v[j];
    }
}

__global__ void k_filledges(const void* __restrict__ ebuf) {
    GDC_WAIT();
    GDC_LAUNCH();
    int e = blockIdx.x * blockDim.x + threadIdx.x;
    if (e >= N_EDGES) return;
    int s, d;
    if (g_is64) {
        const long long* p = (const long long*)ebuf;
        s = (int)p[e]; d = (int)p[N_EDGES + e];
    } else {
        const int* p = (const int*)ebuf;
        s = p[e]; d = p[N_EDGES + e];
    }
    int pos = atomicAdd(&g_cursor[d], 1);
    g_csrsrc[pos] = s;
}

// ---------------- layer-0 aggregate (fused prescale): x -> g_hx fp16 -------
__global__ void k_agg0(const float* __restrict__ x) {
    GDC_WAIT();
    GDC_LAUNCH();
    int gwarp = (blockIdx.x * blockDim.x + threadIdx.x) >> 5;
    int lane = threadIdx.x & 31;
    if (gwarp >= N_NODES) return;
    int n = gwarp;
    int beg = g_colptr[n], end = g_colptr[n + 1];
    float a = 0.f, a32 = 0.f;
    for (int i = beg; i < end; i++) {
        int s = g_csrsrc[i];                 // broadcast
        float ds = g_dis[s];                 // broadcast
        a = fmaf(ds, x[s * K0 + lane], a);
        if (lane == 0) a32 = fmaf(ds, x[s * K0 + 32], a32);
    }
    float dn = g_dis[n];
    g_hx[n * K0P + lane] = __float2half(a * dn);
    if (lane == 0) g_hx[n * K0P + 32] = __float2half(a32 * dn);
    else if (lane < 4) g_hx[n * K0P + 32 + lane] = __float2half(0.f);
}

// ---------------- tensor-core GEMM: BM=128, 8 warps, dynamic smem ----------
// PDL: B-tile fill (weights, >=2 kernels upstream) runs BEFORE griddep wait.
// MODE 0: A=g_hx [N,36] -> g_h fp16, epi = BN(layer0)+ReLU
// MODE 1: A=g_h  [N,100] -> g_Y fp16, epi = *dis[row]
template <int KPAD, int KA, int MODE>
__global__ void __launch_bounds__(256) k_mma(const __half* __restrict__ Wp) {
    constexpr int KS = KPAD + 8;
    constexpr int C2 = KA / 2;
    constexpr int P2 = (KPAD - KA) / 2;
    extern __shared__ __half smem[];
    __half* As = smem;                 // [128][KS]
    __half* Bs = smem + 128 * KS;      // [104][KS]
    int row0 = blockIdx.x * 128;
    int tid = threadIdx.x;
    const __half2 z2 = __float2half2_rn(0.f);

    // preamble (safe: weights written by k_init/prep, far upstream)
    for (int i = tid; i < 104 * (KPAD / 2); i += 256) {
        int nn = i / (KPAD / 2), c2 = i % (KPAD / 2);
        __half2 v = ((const __half2*)Wp)[i];
        *(__half2*)&Bs[nn * KS + c2 * 2] = v;
    }
    for (int i = tid; i < 128 * P2; i += 256) {
        int r = i / P2, j = i % P2;
        *(__half2*)&As[r * KS + KA + j * 2] = z2;
    }

    GDC_WAIT();
    GDC_LAUNCH();

    const __half* Asrc = (MODE == 0) ? g_hx : g_h;
    for (int i = tid; i < 128 * C2; i += 256) {
        int r = i / C2, c2 = i % C2;
        int gr = row0 + r;
        __half2 v = (gr < N_NODES) ? ((const __half2*)Asrc)[gr * C2 + c2] : z2;
        *(__half2*)&As[r * KS + c2 * 2] = v;
    }
    __syncthreads();

    int warp = tid >> 5, lane = tid & 31;
    int g = lane >> 2, t = lane & 3;
    int r0 = warp * 16;
    float acc[13][4];
#pragma unroll
    for (int j = 0; j < 13; j++)
#pragma unroll
        for (int c = 0; c < 4; c++) acc[j][c] = 0.f;

#pragma unroll
    for (int ks = 0; ks < KPAD / 16; ks++) {
        int kb = ks * 16 + t * 2;
        unsigned a0 = *(unsigned*)&As[(r0 + g) * KS + kb];
        unsigned a1 = *(unsigned*)&As[(r0 + g + 8) * KS + kb];
        unsigned a2 = *(unsigned*)&As[(r0 + g) * KS + kb + 8];
        unsigned a3 = *(unsigned*)&As[(r0 + g + 8) * KS + kb + 8];
#pragma unroll
        for (int j = 0; j < 13; j++) {
            int nr = j * 8 + g;
            unsigned b0 = *(unsigned*)&Bs[nr * KS + kb];
            unsigned b1 = *(unsigned*)&Bs[nr * KS + kb + 8];
            asm volatile(
                "mma.sync.aligned.m16n8k16.row.col.f32.f16.f16.f32 "
                "{%0,%1,%2,%3}, {%4,%5,%6,%7}, {%8,%9}, {%0,%1,%2,%3};"
                : "+f"(acc[j][0]), "+f"(acc[j][1]), "+f"(acc[j][2]), "+f"(acc[j][3])
                : "r"(a0), "r"(a1), "r"(a2), "r"(a3), "r"(b0), "r"(b1));
        }
    }

    int gr0 = row0 + r0 + g;
    int gr1 = gr0 + 8;
    if (MODE == 0) {
#pragma unroll
        for (int j = 0; j < 13; j++) {
            int c = j * 8 + t * 2;
            if (c >= H) continue;
            float Sx = g_bnS[c], Sy = g_bnS[c + 1];
            float Tx = g_bnT[c], Ty = g_bnT[c + 1];
            if (gr0 < N_NODES) {
                float ox = fmaxf(fmaf(acc[j][0], Sx, Tx), 0.f);
                float oy = fmaxf(fmaf(acc[j][1], Sy, Ty), 0.f);
                __half2 hv = __floats2half2_rn(ox, oy);
                *(__half2*)&g_h[gr0 * H + c] = hv;
            }
            if (gr1 < N_NODES) {
                float ox = fmaxf(fmaf(acc[j][2], Sx, Tx), 0.f);
                float oy = fmaxf(fmaf(acc[j][3], Sy, Ty), 0.f);
                __half2 hv = __floats2half2_rn(ox, oy);
                *(__half2*)&g_h[gr1 * H + c] = hv;
            }
        }
    } else {
        float d0 = (gr0 < N_NODES) ? g_dis[gr0] : 0.f;
        float d1 = (gr1 < N_NODES) ? g_dis[gr1] : 0.f;
#pragma unroll
        for (int j = 0; j < 13; j++) {
            int c = j * 8 + t * 2;
            if (c >= H) continue;
            if (gr0 < N_NODES) {
                __half2 hv = __floats2half2_rn(acc[j][0] * d0, acc[j][1] * d0);
                *(__half2*)&g_Y[gr0 * H + c] = hv;
            }
            if (gr1 < N_NODES) {
                __half2 hv = __floats2half2_rn(acc[j][2] * d1, acc[j][3] * d1);
                *(__half2*)&g_Y[gr1 * H + c] = hv;
            }
        }
    }
}

// ---------------- aggregation: g_Y(fp16) -> g_h(fp16)  [LAST: fused pool] --
template <int LAST>
__global__ void k_agg(int layer, int relu, const float* __restrict__ hW) {
    GDC_WAIT();
    GDC_LAUNCH();
    int gwarp = (blockIdx.x * blockDim.x + threadIdx.x) >> 5;
    int lane = threadIdx.x & 31;
    if (gwarp >= N_NODES) return;
    int n = gwarp;
    float ox = 0.f, oy = 0.f, oz = 0.f, ow = 0.f;
    if (lane < H4) {
        int beg = g_colptr[n], end = g_colptr[n + 1];
        const uint2* Y2 = (const uint2*)g_Y;
        float a0x=0.f,a0y=0.f,a0z=0.f,a0w=0.f;
        float a1x=0.f,a1y=0.f,a1z=0.f,a1w=0.f;
        float a2x=0.f,a2y=0.f,a2z=0.f,a2w=0.f;
        float a3x=0.f,a3y=0.f,a3z=0.f,a3w=0.f;
        int i = beg;
        for (; i + 3 < end; i += 4) {
            int s0 = g_csrsrc[i], s1 = g_csrsrc[i+1], s2 = g_csrsrc[i+2], s3 = g_csrsrc[i+3];
            uint2 u0 = Y2[s0 * H4 + lane];
            uint2 u1 = Y2[s1 * H4 + lane];
            uint2 u2 = Y2[s2 * H4 + lane];
            uint2 u3 = Y2[s3 * H4 + lane];
            float2 p;
            p = __half22float2(*(__half2*)&u0.x); a0x += p.x; a0y += p.y;
            p = __half22float2(*(__half2*)&u0.y); a0z += p.x; a0w += p.y;
            p = __half22float2(*(__half2*)&u1.x); a1x += p.x; a1y += p.y;
            p = __half22float2(*(__half2*)&u1.y); a1z += p.x; a1w += p.y;
            p = __half22float2(*(__half2*)&u2.x); a2x += p.x; a2y += p.y;
            p = __half22float2(*(__half2*)&u2.y); a2z += p.x; a2w += p.y;
            p = __half22float2(*(__half2*)&u3.x); a3x += p.x; a3y += p.y;
            p = __half22float2(*(__half2*)&u3.y); a3z += p.x; a3w += p.y;
        }
        for (; i < end; i++) {
            int s0 = g_csrsrc[i];
            uint2 u0 = Y2[s0 * H4 + lane];
            float2 p;
            p = __half22float2(*(__half2*)&u0.x); a0x += p.x; a0y += p.y;
            p = __half22float2(*(__half2*)&u0.y); a0z += p.x; a0w += p.y;
        }
        float ax = (a0x + a1x) + (a2x + a3x);
        float ay = (a0y + a1y) + (a2y + a3y);
        float az = (a0z + a1z) + (a2z + a3z);
        float aw = (a0w + a1w) + (a2w + a3w);
        float d = g_dis[n];
        int c = layer * H + lane * 4;
        float4 S = *(const float4*)&g_bnS[c];
        float4 T = *(const float4*)&g_bnT[c];
        ox = fmaf(ax * d, S.x, T.x);
        oy = fmaf(ay * d, S.y, T.y);
        oz = fmaf(az * d, S.z, T.z);
        ow = fmaf(aw * d, S.w, T.w);
        if (relu) {
            ox = fmaxf(ox, 0.f); oy = fmaxf(oy, 0.f);
            oz = fmaxf(oz, 0.f); ow = fmaxf(ow, 0.f);
        }
    }
    if (LAST == 0) {
        if (lane < H4) {
            __half2 h0 = __floats2half2_rn(ox, oy);
            __half2 h1 = __floats2half2_rn(oz, ow);
            uint2 u; u.x = *(unsigned*)&h0; u.y = *(unsigned*)&h1;
            *(uint2*)&g_h[n * H + lane * 4] = u;
        }
    } else {
        float s = 0.f;
        if (lane < H4) {
            float4 w4 = ((const float4*)hW)[lane];
            s = ox * w4.x + oy * w4.y + oz * w4.z + ow * w4.w;
        }
#pragma unroll
        for (int off = 16; off > 0; off >>= 1)
            s += __shfl_down_sync(0xffffffffu, s, off);
        if (lane == 0) atomicAdd(&g_gsum[g_batch[n]], s);
    }
}

// ---------------- finish: bias + LeakyReLU ----------------
__global__ void k_finish(const float* __restrict__ hb, float* __restrict__ out) {
    GDC_WAIT();
    int g = blockIdx.x * blockDim.x + threadIdx.x;
    if (g >= N_GRAPHSX) return;
    float o = g_gsum[g] + hb[0];
    out[g] = (o >= 0.f) ? o : 0.1f * o;
}

// ---------------- PDL launch helper ----------------
template <typename... Args>
static void pdl_launch(void (*fn)(Args...), dim3 grid, dim3 block, size_t smem, Args... args) {
    void* pargs[sizeof...(Args)] = { (void*)&args... };
    cudaLaunchConfig_t cfg = {};
    cfg.gridDim = grid;
    cfg.blockDim = block;
    cfg.dynamicSmemBytes = smem;
    cfg.stream = 0;
    cudaLaunchAttribute attr;
    attr.id = cudaLaunchAttributeProgrammaticStreamSerialization;
    attr.val.programmaticStreamSerializationAllowed = 1;
    cfg.attrs = &attr;
    cfg.numAttrs = 1;
    cudaLaunchKernelExC(&cfg, (const void*)fn, pargs);
}

// ---------------- launch ----------------
extern "C" void kernel_launch(void* const* d_in, const int* in_sizes, int n_in,
                              void* d_out, int out_size) {
    const float* x      = (const float*)d_in[0];
    const void*  ei     = d_in[1];
    const void*  batch  = d_in[2];
    const float* W0     = (const float*)d_in[3];
    const float* Ws     = (const float*)d_in[4];
    const float* biases = (const float*)d_in[5];
    const float* gamma  = (const float*)d_in[6];
    const float* beta   = (const float*)d_in[7];
    const float* mean   = (const float*)d_in[8];
    const float* var    = (const float*)d_in[9];
    const float* headW  = (const float*)d_in[10];
    const float* headb  = (const float*)d_in[11];
    float* out = (float*)d_out;

    const int smem_big   = (128 + 104) * (112 + 8) * 2;  // 55680
    const int smem_small = (128 + 104) * (48 + 8) * 2;   // 25984
    cudaFuncSetAttribute(k_mma<112, 100, 1>, cudaFuncAttributeMaxDynamicSharedMemorySize, smem_big);
    cudaFuncSetAttribute(k_mma<48, 36, 0>,   cudaFuncAttributeMaxDynamicSharedMemorySize, smem_small);

    __half* whp = nullptr;
    cudaGetSymbolAddress((void**)&whp, g_Wh);

    int mma_blocks = (N_NODES + 127) / 128;
    int agg_blocks = (N_NODES * 32 + 255) / 256;

    // full PDL chain — every boundary overlaps predecessor tail
    pdl_launch(k_init, dim3((N_NODES + 255) / 256), dim3(256), (size_t)0,
               (const unsigned*)ei, (const float*)W0, (const float*)Ws,
               (const float*)biases, (const float*)gamma, (const float*)beta,
               (const float*)mean, (const float*)var);
    pdl_launch(k_count, dim3((N_EDGES + 255) / 256), dim3(256), (size_t)0,
               (const void*)ei, (const void*)batch);
    pdl_launch(k_scan_a, dim3(NBLK_SCAN), dim3(256), (size_t)0);
    pdl_launch(k_scan_b, dim3(1), dim3(32), (size_t)0);
    pdl_launch(k_scan_c, dim3(NBLK_SCAN), dim3(256), (size_t)0);
    pdl_launch(k_filledges, dim3((N_EDGES + 255) / 256), dim3(256), (size_t)0,
               (const void*)ei);
    pdl_launch(k_agg0, dim3(agg_blocks), dim3(256), (size_t)0, (const float*)x);
    pdl_launch(k_mma<48, 36, 0>, dim3(mma_blocks), dim3(256), (size_t)smem_small,
               (const __half*)whp);
    for (int l = 1; l < 4; l++) {
        pdl_launch(k_mma<112, 100, 1>, dim3(mma_blocks), dim3(256), (size_t)smem_big,
                   (const __half*)(whp + l * WSL));
        if (l < 3) pdl_launch(k_agg<0>, dim3(agg_blocks), dim3(256), (size_t)0,
                              (int)l, (int)1, (const float*)headW);
        else       pdl_launch(k_agg<1>, dim3(agg_blocks), dim3(256), (size_t)0,
                              (int)l, (int)0, (const float*)headW);
    }
    pdl_launch(k_finish, dim3((N_GRAPHSX + 255) / 256), dim3(256), (size_t)0,
               (const float*)headb, (float*)out);
}